// round 15
// baseline (speedup 1.0000x reference)
#include <cuda_runtime.h>
#include <cuda_fp16.h>
#include <math.h>

#define N_NODES   100000
#define N_EDGES   1600000
#define N_FEAT    128
#define HIDDEN    16
#define EMBED     128
#define N_GRAPHS  64

// ---------------- scratch (device globals; no allocation allowed) ----------
// Zero-initialized at load; cross-call resets of g_degi/g_pool/g_cnt are
// folded into k_relu (after last reader, before next user).
__device__ __align__(16) int    g_degi[N_NODES];
__device__ __align__(16) float  g_dinv[N_NODES];
__device__ __align__(16) __half g_h1  [N_NODES * HIDDEN];   // x@W1, fp16
__device__ __align__(16) __half g_hs1 [N_NODES * HIDDEN];   // dinv*h1, fp16
__device__ __align__(16) __half g_agg1[N_NODES * HIDDEN];   // fp16 accumulator
__device__ __align__(16) __half g_hs2 [N_NODES * HIDDEN];   // dinv*hrelu, fp16
__device__ __align__(16) __half g_agg2[N_NODES * HIDDEN];   // fp16 accumulator
__device__ __align__(16) float  g_pool[N_GRAPHS * HIDDEN];
__device__ __align__(16) float  g_cnt [N_GRAPHS];

// ---------------- packed-math helpers ---------------------------------------
__device__ __forceinline__ unsigned long long pack2(float a, float b) {
    unsigned long long r;
    asm("mov.b64 %0, {%1, %2};" : "=l"(r) : "f"(a), "f"(b));
    return r;
}
__device__ __forceinline__ unsigned long long fma2(unsigned long long a,
                                                   unsigned long long b,
                                                   unsigned long long c) {
    unsigned long long d;
    asm("fma.rn.f32x2 %0, %1, %2, %3;" : "=l"(d) : "l"(a), "l"(b), "l"(c));
    return d;
}
// f32x2 (packed in u64) -> half2 (packed in u32)
__device__ __forceinline__ unsigned ull2h2(unsigned long long v) {
    float lo, hi;
    asm("mov.b64 {%0, %1}, %2;" : "=f"(lo), "=f"(hi) : "l"(v));
    __half2 h = __floats2half2_rn(lo, hi);
    return *(unsigned*)&h;
}
__device__ __forceinline__ void red16(__half* p, uint4 u) {
    asm volatile("red.global.add.noftz.v4.f16x2 [%0], {%1,%2,%3,%4};"
                 :: "l"(p), "r"(u.x), "r"(u.y), "r"(u.z), "r"(u.w) : "memory");
}

// ---------------- K_main: fused [GEMM1 h1 = x@W1 (fp16 out)] + [degree] ----
// NPB=256 (1 node/thread): smem 24.4KB -> many co-resident GEMM blocks, so
// one block's FFMA phase overlaps another's HBM loads.
#define NPB   256
#define KC    16
#define PITCH 257
#define GEMM_BLOCKS ((N_NODES + NPB - 1) / NPB)   // 391
#define DEG_BLOCKS  (N_EDGES / 256)               // 6250
__global__ __launch_bounds__(256) void k_main(const float4* __restrict__ x4,
                                              const float*  __restrict__ W1,
                                              const int*    __restrict__ dst) {
    if (blockIdx.x >= GEMM_BLOCKS) {
        int e = (blockIdx.x - GEMM_BLOCKS) * 256 + threadIdx.x;
        if (e < N_EDGES) atomicAdd(&g_degi[dst[e]], 1);
        return;
    }

    __shared__ float xs[KC * PITCH];                     // k-major x tile
    __shared__ unsigned long long Wp[N_FEAT * HIDDEN/2]; // packed W pairs

    int tid = threadIdx.x;
    for (int i = tid; i < N_FEAT * HIDDEN / 2; i += 256) {
        float2 w = ((const float2*)W1)[i];
        Wp[i] = pack2(w.x, w.y);
    }

    int base = blockIdx.x * NPB;
    int na = base + tid;

    unsigned long long acc[8];
    unsigned long long z = pack2(0.0f, 0.0f);
#pragma unroll
    for (int p = 0; p < 8; p++) acc[p] = z;

    for (int c = 0; c < N_FEAT / KC; c++) {
        __syncthreads();
#pragma unroll
        for (int i = 0; i < 4; i++) {
            int idx = i * 256 + tid;
            int q = idx & 3;
            int n = idx >> 2;
            int gn = base + n;
            if (gn >= N_NODES) gn = 0;
            float4 v = x4[gn * (N_FEAT/4) + c * (KC/4) + q];
            int kb = 4 * q;
            xs[(kb + 0) * PITCH + n] = v.x;
            xs[(kb + 1) * PITCH + n] = v.y;
            xs[(kb + 2) * PITCH + n] = v.z;
            xs[(kb + 3) * PITCH + n] = v.w;
        }
        __syncthreads();

#pragma unroll
        for (int k = 0; k < KC; k++) {
            float xa = xs[k * PITCH + tid];
            unsigned long long xa2 = pack2(xa, xa);
            int kg = c * KC + k;
#pragma unroll
            for (int p2 = 0; p2 < 4; p2++) {
                ulonglong2 w = *((const ulonglong2*)&Wp[kg * 8 + 2 * p2]);
                acc[2*p2]   = fma2(xa2, w.x, acc[2*p2]);
                acc[2*p2+1] = fma2(xa2, w.y, acc[2*p2+1]);
            }
        }
    }

    if (na < N_NODES) {
        uint4 o0, o1;
        o0.x = ull2h2(acc[0]); o0.y = ull2h2(acc[1]);
        o0.z = ull2h2(acc[2]); o0.w = ull2h2(acc[3]);
        o1.x = ull2h2(acc[4]); o1.y = ull2h2(acc[5]);
        o1.z = ull2h2(acc[6]); o1.w = ull2h2(acc[7]);
        ((uint4*)g_h1)[na * 2]     = o0;
        ((uint4*)g_h1)[na * 2 + 1] = o1;
    }
}

// ---- K_self: dinv = rsqrt(1+deg); hs1 = agg1 seed = dinv*h1 (fp16 in/out) -
__global__ void k_self() {
    int idx = blockIdx.x * blockDim.x + threadIdx.x;   // over uint4 (8 halves)
    if (idx >= N_NODES * 2) return;
    int node = idx >> 1;
    float di = rsqrtf(1.0f + (float)g_degi[node]);
    if ((idx & 1) == 0) g_dinv[node] = di;
    uint4 u = ((const uint4*)g_h1)[idx];
    float2 f0 = __half22float2(*(__half2*)&u.x);
    float2 f1 = __half22float2(*(__half2*)&u.y);
    float2 f2 = __half22float2(*(__half2*)&u.z);
    float2 f3 = __half22float2(*(__half2*)&u.w);
    __half2 h0 = __floats2half2_rn(f0.x * di, f0.y * di);
    __half2 h1 = __floats2half2_rn(f1.x * di, f1.y * di);
    __half2 h2 = __floats2half2_rn(f2.x * di, f2.y * di);
    __half2 h3 = __floats2half2_rn(f3.x * di, f3.y * di);
    uint4 o;
    o.x = *(unsigned*)&h0; o.y = *(unsigned*)&h1;
    o.z = *(unsigned*)&h2; o.w = *(unsigned*)&h3;
    ((uint4*)g_hs1)[idx]  = o;
    ((uint4*)g_agg1)[idx] = o;   // self-loop seed
}

// ---- K_scatter1: 2 adjacent edges/thread, int2 index loads, fp16 red ------
#define EHALF (N_EDGES / 2)
__global__ void k_scatter1(const int* __restrict__ src,
                           const int* __restrict__ dst) {
    int t = blockIdx.x * blockDim.x + threadIdx.x;
    if (t >= EHALF) return;
    int2 s2 = __ldg(&((const int2*)src)[t]);   // edges 2t, 2t+1
    int2 d2 = __ldg(&((const int2*)dst)[t]);
    const uint4* hs = (const uint4*)g_hs1;
    uint4 a0 = __ldg(&hs[s2.x * 2]);
    uint4 a1 = __ldg(&hs[s2.x * 2 + 1]);
    uint4 b0 = __ldg(&hs[s2.y * 2]);
    uint4 b1 = __ldg(&hs[s2.y * 2 + 1]);
    __half* pa = g_agg1 + d2.x * HIDDEN;
    __half* pb = g_agg1 + d2.y * HIDDEN;
    red16(pa,     a0);
    red16(pa + 8, a1);
    red16(pb,     b0);
    red16(pb + 8, b1);
}

// ---- K_relu: relu layer + fold-in resets of degi/pool/cnt for next call ---
__global__ void k_relu(const float* __restrict__ b1) {
    int idx = blockIdx.x * blockDim.x + threadIdx.x;    // over uint4 (8 halves)
    if (idx < N_NODES / 4) ((int4*)g_degi)[idx] = make_int4(0, 0, 0, 0);
    if (idx < N_GRAPHS * HIDDEN / 4)
        ((float4*)g_pool)[idx] = make_float4(0.f, 0.f, 0.f, 0.f);
    if (idx < N_GRAPHS / 4)
        ((float4*)g_cnt)[idx] = make_float4(0.f, 0.f, 0.f, 0.f);

    if (idx >= N_NODES * 2) return;
    int node  = idx >> 1;
    int half8 = idx & 1;
    float di = g_dinv[node];
    uint4 u = ((const uint4*)g_agg1)[idx];
    float4 blo = ((const float4*)b1)[half8 * 2];
    float4 bhi = ((const float4*)b1)[half8 * 2 + 1];
    float2 f0 = __half22float2(*(__half2*)&u.x);
    float2 f1 = __half22float2(*(__half2*)&u.y);
    float2 f2 = __half22float2(*(__half2*)&u.z);
    float2 f3 = __half22float2(*(__half2*)&u.w);
    f0.x = fmaxf(fmaf(di, f0.x, blo.x), 0.0f) * di;
    f0.y = fmaxf(fmaf(di, f0.y, blo.y), 0.0f) * di;
    f1.x = fmaxf(fmaf(di, f1.x, blo.z), 0.0f) * di;
    f1.y = fmaxf(fmaf(di, f1.y, blo.w), 0.0f) * di;
    f2.x = fmaxf(fmaf(di, f2.x, bhi.x), 0.0f) * di;
    f2.y = fmaxf(fmaf(di, f2.y, bhi.y), 0.0f) * di;
    f3.x = fmaxf(fmaf(di, f3.x, bhi.z), 0.0f) * di;
    f3.y = fmaxf(fmaf(di, f3.y, bhi.w), 0.0f) * di;
    __half2 h0 = __floats2half2_rn(f0.x, f0.y);
    __half2 h1 = __floats2half2_rn(f1.x, f1.y);
    __half2 h2 = __floats2half2_rn(f2.x, f2.y);
    __half2 h3 = __floats2half2_rn(f3.x, f3.y);
    uint4 o;
    o.x = *(unsigned*)&h0; o.y = *(unsigned*)&h1;
    o.z = *(unsigned*)&h2; o.w = *(unsigned*)&h3;
    ((uint4*)g_hs2)[idx]  = o;
    ((uint4*)g_agg2)[idx] = o;   // self-loop seed
}

// ---- K_scatter2: 2 adjacent edges/thread, int2 index loads, fp16 red ------
__global__ void k_scatter2(const int* __restrict__ src,
                           const int* __restrict__ dst) {
    int t = blockIdx.x * blockDim.x + threadIdx.x;
    if (t >= EHALF) return;
    int2 s2 = __ldg(&((const int2*)src)[t]);   // edges 2t, 2t+1
    int2 d2 = __ldg(&((const int2*)dst)[t]);
    const uint4* hs = (const uint4*)g_hs2;
    uint4 a0 = __ldg(&hs[s2.x * 2]);
    uint4 a1 = __ldg(&hs[s2.x * 2 + 1]);
    uint4 b0 = __ldg(&hs[s2.y * 2]);
    uint4 b1 = __ldg(&hs[s2.y * 2 + 1]);
    __half* pa = g_agg2 + d2.x * HIDDEN;
    __half* pb = g_agg2 + d2.y * HIDDEN;
    red16(pa,     a0);
    red16(pa + 8, a1);
    red16(pb,     b0);
    red16(pb + 8, b1);
}

// ---- K_pool: pool += dinv[n]*agg2[n]  (batch sorted, run-length) ----------
#define POOL_CHUNK 32
__global__ void k_pool(const int* __restrict__ batch) {
    int t = blockIdx.x * blockDim.x + threadIdx.x;
    const int n_chunks = N_NODES / POOL_CHUNK;
    if (t >= n_chunks * HIDDEN) return;
    int c = t >> 4;
    int j = t & 15;
    int n0 = c * POOL_CHUNK;

    int   curg = __ldg(&batch[n0]);
    float acc  = 0.0f;
    float accc = 0.0f;
    for (int n = n0; n < n0 + POOL_CHUNK; n++) {
        int g = __ldg(&batch[n]);
        if (g != curg) {
            atomicAdd(&g_pool[curg * HIDDEN + j], acc);
            if (j == 0) atomicAdd(&g_cnt[curg], accc);
            acc = 0.0f; accc = 0.0f; curg = g;
        }
        float v = __half2float(g_agg2[n * HIDDEN + j]);
        acc  = fmaf(g_dinv[n], v, acc);
        accc += 1.0f;
    }
    atomicAdd(&g_pool[curg * HIDDEN + j], acc);
    if (j == 0) atomicAdd(&g_cnt[curg], accc);
}

// ---- K_final: out = (pool/cnt) @ W2 + b2 -----------------------------------
__global__ void k_final(const float* __restrict__ W2,
                        const float* __restrict__ b2,
                        float* __restrict__ out) {
    int t = blockIdx.x * blockDim.x + threadIdx.x;
    if (t >= N_GRAPHS * EMBED) return;
    int g = t >> 7;
    int e = t & 127;
    float inv = 1.0f / fmaxf(g_cnt[g], 1.0f);
    float sum = 0.0f;
#pragma unroll
    for (int k = 0; k < HIDDEN; k++)
        sum += g_pool[g * HIDDEN + k] * W2[k * EMBED + e];
    out[t] = b2[e] + inv * sum;
}

// ---------------- launch ----------------------------------------------------
extern "C" void kernel_launch(void* const* d_in, const int* in_sizes, int n_in,
                              void* d_out, int out_size) {
    const float* x     = (const float*)d_in[0];
    const int*   ei    = (const int*)  d_in[1];
    const int*   batch = (const int*)  d_in[2];
    const float* W1    = (const float*)d_in[3];
    const float* b1    = (const float*)d_in[4];
    const float* W2    = (const float*)d_in[5];
    const float* b2    = (const float*)d_in[6];
    float* out = (float*)d_out;

    const int* src = ei;
    const int* dst = ei + N_EDGES;

    k_main<<<GEMM_BLOCKS + DEG_BLOCKS, 256>>>((const float4*)x, W1, dst);
    k_self<<<(N_NODES * 2 + 255) / 256, 256>>>();
    k_scatter1<<<(EHALF + 255) / 256, 256>>>(src, dst);
    k_relu<<<(N_NODES * 2 + 255) / 256, 256>>>(b1);
    k_scatter2<<<(EHALF + 255) / 256, 256>>>(src, dst);
    k_pool<<<((N_NODES / POOL_CHUNK) * HIDDEN + 255) / 256, 256>>>(batch);
    k_final<<<(N_GRAPHS * EMBED + 255) / 256, 256>>>(W2, b2, out);
}

// round 16
// speedup vs baseline: 1.0249x; 1.0249x over previous
#include <cuda_runtime.h>
#include <cuda_fp16.h>
#include <math.h>

#define N_NODES   100000
#define N_EDGES   1600000
#define N_FEAT    128
#define HIDDEN    16
#define EMBED     128
#define N_GRAPHS  64

// ---------------- scratch (device globals; no allocation allowed) ----------
// Zero-initialized at load; cross-call resets of g_degi/g_pool/g_cnt are
// folded into k_relu (after last reader, before next user).
__device__ __align__(16) int    g_degi[N_NODES];
__device__ __align__(16) float  g_dinv[N_NODES];
__device__ __align__(16) __half g_h1  [N_NODES * HIDDEN];   // x@W1, fp16
__device__ __align__(16) __half g_hs1 [N_NODES * HIDDEN];   // dinv*h1, fp16
__device__ __align__(16) __half g_agg1[N_NODES * HIDDEN];   // fp16 accumulator
__device__ __align__(16) __half g_hs2 [N_NODES * HIDDEN];   // dinv*hrelu, fp16
__device__ __align__(16) __half g_agg2[N_NODES * HIDDEN];   // fp16 accumulator
__device__ __align__(16) float  g_pool[N_GRAPHS * HIDDEN];
__device__ __align__(16) float  g_cnt [N_GRAPHS];

// ---------------- packed-math helpers ---------------------------------------
__device__ __forceinline__ unsigned long long pack2(float a, float b) {
    unsigned long long r;
    asm("mov.b64 %0, {%1, %2};" : "=l"(r) : "f"(a), "f"(b));
    return r;
}
__device__ __forceinline__ unsigned long long fma2(unsigned long long a,
                                                   unsigned long long b,
                                                   unsigned long long c) {
    unsigned long long d;
    asm("fma.rn.f32x2 %0, %1, %2, %3;" : "=l"(d) : "l"(a), "l"(b), "l"(c));
    return d;
}
// f32x2 (packed in u64) -> half2 (packed in u32)
__device__ __forceinline__ unsigned ull2h2(unsigned long long v) {
    float lo, hi;
    asm("mov.b64 {%0, %1}, %2;" : "=f"(lo), "=f"(hi) : "l"(v));
    __half2 h = __floats2half2_rn(lo, hi);
    return *(unsigned*)&h;
}
__device__ __forceinline__ void red16(__half* p, uint4 u) {
    asm volatile("red.global.add.noftz.v4.f16x2 [%0], {%1,%2,%3,%4};"
                 :: "l"(p), "r"(u.x), "r"(u.y), "r"(u.z), "r"(u.w) : "memory");
}

// ---------------- K_main: fused [GEMM1 h1 = x@W1 (fp16 out)] + [degree] ----
// GEMM: NPB=512, 2 nodes/thread (round-14 validated shape).
// Degree: 4 edges/thread via int4 loads.
#define NPB   512
#define KC    16
#define PITCH 513
#define GEMM_BLOCKS ((N_NODES + NPB - 1) / NPB)   // 196
#define DEG_BLOCKS  (N_EDGES / 1024)              // 1563 (4 edges/thread)
__global__ __launch_bounds__(256) void k_main(const float4* __restrict__ x4,
                                              const float*  __restrict__ W1,
                                              const int*    __restrict__ dst) {
    if (blockIdx.x >= GEMM_BLOCKS) {
        int t = (blockIdx.x - GEMM_BLOCKS) * 256 + threadIdx.x;
        if (t < N_EDGES / 4) {
            int4 d4 = __ldg(&((const int4*)dst)[t]);
            atomicAdd(&g_degi[d4.x], 1);
            atomicAdd(&g_degi[d4.y], 1);
            atomicAdd(&g_degi[d4.z], 1);
            atomicAdd(&g_degi[d4.w], 1);
        }
        return;
    }

    __shared__ float xs[KC * PITCH];                     // k-major x tile
    __shared__ unsigned long long Wp[N_FEAT * HIDDEN/2]; // packed W pairs

    int tid = threadIdx.x;
    for (int i = tid; i < N_FEAT * HIDDEN / 2; i += 256) {
        float2 w = ((const float2*)W1)[i];
        Wp[i] = pack2(w.x, w.y);
    }

    int base = blockIdx.x * NPB;
    int na = base + tid;
    int nb = na + 256;

    unsigned long long accA[8], accB[8];
    unsigned long long z = pack2(0.0f, 0.0f);
#pragma unroll
    for (int p = 0; p < 8; p++) { accA[p] = z; accB[p] = z; }

    for (int c = 0; c < N_FEAT / KC; c++) {
        __syncthreads();
#pragma unroll
        for (int i = 0; i < 8; i++) {
            int idx = i * 256 + tid;
            int q = idx & 3;
            int n = idx >> 2;
            int gn = base + n;
            if (gn >= N_NODES) gn = 0;
            float4 v = x4[gn * (N_FEAT/4) + c * (KC/4) + q];
            int kb = 4 * q;
            xs[(kb + 0) * PITCH + n] = v.x;
            xs[(kb + 1) * PITCH + n] = v.y;
            xs[(kb + 2) * PITCH + n] = v.z;
            xs[(kb + 3) * PITCH + n] = v.w;
        }
        __syncthreads();

#pragma unroll
        for (int k = 0; k < KC; k++) {
            float xa = xs[k * PITCH + tid];
            float xb = xs[k * PITCH + tid + 256];
            unsigned long long xa2 = pack2(xa, xa);
            unsigned long long xb2 = pack2(xb, xb);
            int kg = c * KC + k;
#pragma unroll
            for (int p2 = 0; p2 < 4; p2++) {
                ulonglong2 w = *((const ulonglong2*)&Wp[kg * 8 + 2 * p2]);
                accA[2*p2]   = fma2(xa2, w.x, accA[2*p2]);
                accA[2*p2+1] = fma2(xa2, w.y, accA[2*p2+1]);
                accB[2*p2]   = fma2(xb2, w.x, accB[2*p2]);
                accB[2*p2+1] = fma2(xb2, w.y, accB[2*p2+1]);
            }
        }
    }

    if (na < N_NODES) {
        uint4 o0, o1;
        o0.x = ull2h2(accA[0]); o0.y = ull2h2(accA[1]);
        o0.z = ull2h2(accA[2]); o0.w = ull2h2(accA[3]);
        o1.x = ull2h2(accA[4]); o1.y = ull2h2(accA[5]);
        o1.z = ull2h2(accA[6]); o1.w = ull2h2(accA[7]);
        ((uint4*)g_h1)[na * 2]     = o0;
        ((uint4*)g_h1)[na * 2 + 1] = o1;
    }
    if (nb < N_NODES) {
        uint4 o0, o1;
        o0.x = ull2h2(accB[0]); o0.y = ull2h2(accB[1]);
        o0.z = ull2h2(accB[2]); o0.w = ull2h2(accB[3]);
        o1.x = ull2h2(accB[4]); o1.y = ull2h2(accB[5]);
        o1.z = ull2h2(accB[6]); o1.w = ull2h2(accB[7]);
        ((uint4*)g_h1)[nb * 2]     = o0;
        ((uint4*)g_h1)[nb * 2 + 1] = o1;
    }
}

// ---- K_self: dinv = rsqrt(1+deg); hs1 = agg1 seed = dinv*h1 (fp16 in/out) -
__global__ void k_self() {
    int idx = blockIdx.x * blockDim.x + threadIdx.x;   // over uint4 (8 halves)
    if (idx >= N_NODES * 2) return;
    int node = idx >> 1;
    float di = rsqrtf(1.0f + (float)g_degi[node]);
    if ((idx & 1) == 0) g_dinv[node] = di;
    uint4 u = ((const uint4*)g_h1)[idx];
    float2 f0 = __half22float2(*(__half2*)&u.x);
    float2 f1 = __half22float2(*(__half2*)&u.y);
    float2 f2 = __half22float2(*(__half2*)&u.z);
    float2 f3 = __half22float2(*(__half2*)&u.w);
    __half2 h0 = __floats2half2_rn(f0.x * di, f0.y * di);
    __half2 h1 = __floats2half2_rn(f1.x * di, f1.y * di);
    __half2 h2 = __floats2half2_rn(f2.x * di, f2.y * di);
    __half2 h3 = __floats2half2_rn(f3.x * di, f3.y * di);
    uint4 o;
    o.x = *(unsigned*)&h0; o.y = *(unsigned*)&h1;
    o.z = *(unsigned*)&h2; o.w = *(unsigned*)&h3;
    ((uint4*)g_hs1)[idx]  = o;
    ((uint4*)g_agg1)[idx] = o;   // self-loop seed
}

// ---- K_scatter1: 4 adjacent edges/thread, int4 index loads, fp16 red ------
#define EQ4 (N_EDGES / 4)
__global__ void k_scatter1(const int* __restrict__ src,
                           const int* __restrict__ dst) {
    int t = blockIdx.x * blockDim.x + threadIdx.x;
    if (t >= EQ4) return;
    int4 s4 = __ldg(&((const int4*)src)[t]);   // edges 4t .. 4t+3
    int4 d4 = __ldg(&((const int4*)dst)[t]);
    const uint4* hs = (const uint4*)g_hs1;
    uint4 a0 = __ldg(&hs[s4.x * 2]), a1 = __ldg(&hs[s4.x * 2 + 1]);
    uint4 b0 = __ldg(&hs[s4.y * 2]), b1 = __ldg(&hs[s4.y * 2 + 1]);
    uint4 c0 = __ldg(&hs[s4.z * 2]), c1 = __ldg(&hs[s4.z * 2 + 1]);
    uint4 e0 = __ldg(&hs[s4.w * 2]), e1 = __ldg(&hs[s4.w * 2 + 1]);
    __half* p0 = g_agg1 + d4.x * HIDDEN;
    __half* p1 = g_agg1 + d4.y * HIDDEN;
    __half* p2 = g_agg1 + d4.z * HIDDEN;
    __half* p3 = g_agg1 + d4.w * HIDDEN;
    red16(p0, a0); red16(p0 + 8, a1);
    red16(p1, b0); red16(p1 + 8, b1);
    red16(p2, c0); red16(p2 + 8, c1);
    red16(p3, e0); red16(p3 + 8, e1);
}

// ---- K_relu: relu layer + fold-in resets of degi/pool/cnt for next call ---
__global__ void k_relu(const float* __restrict__ b1) {
    int idx = blockIdx.x * blockDim.x + threadIdx.x;    // over uint4 (8 halves)
    if (idx < N_NODES / 4) ((int4*)g_degi)[idx] = make_int4(0, 0, 0, 0);
    if (idx < N_GRAPHS * HIDDEN / 4)
        ((float4*)g_pool)[idx] = make_float4(0.f, 0.f, 0.f, 0.f);
    if (idx < N_GRAPHS / 4)
        ((float4*)g_cnt)[idx] = make_float4(0.f, 0.f, 0.f, 0.f);

    if (idx >= N_NODES * 2) return;
    int node  = idx >> 1;
    int half8 = idx & 1;
    float di = g_dinv[node];
    uint4 u = ((const uint4*)g_agg1)[idx];
    float4 blo = ((const float4*)b1)[half8 * 2];
    float4 bhi = ((const float4*)b1)[half8 * 2 + 1];
    float2 f0 = __half22float2(*(__half2*)&u.x);
    float2 f1 = __half22float2(*(__half2*)&u.y);
    float2 f2 = __half22float2(*(__half2*)&u.z);
    float2 f3 = __half22float2(*(__half2*)&u.w);
    f0.x = fmaxf(fmaf(di, f0.x, blo.x), 0.0f) * di;
    f0.y = fmaxf(fmaf(di, f0.y, blo.y), 0.0f) * di;
    f1.x = fmaxf(fmaf(di, f1.x, blo.z), 0.0f) * di;
    f1.y = fmaxf(fmaf(di, f1.y, blo.w), 0.0f) * di;
    f2.x = fmaxf(fmaf(di, f2.x, bhi.x), 0.0f) * di;
    f2.y = fmaxf(fmaf(di, f2.y, bhi.y), 0.0f) * di;
    f3.x = fmaxf(fmaf(di, f3.x, bhi.z), 0.0f) * di;
    f3.y = fmaxf(fmaf(di, f3.y, bhi.w), 0.0f) * di;
    __half2 h0 = __floats2half2_rn(f0.x, f0.y);
    __half2 h1 = __floats2half2_rn(f1.x, f1.y);
    __half2 h2 = __floats2half2_rn(f2.x, f2.y);
    __half2 h3 = __floats2half2_rn(f3.x, f3.y);
    uint4 o;
    o.x = *(unsigned*)&h0; o.y = *(unsigned*)&h1;
    o.z = *(unsigned*)&h2; o.w = *(unsigned*)&h3;
    ((uint4*)g_hs2)[idx]  = o;
    ((uint4*)g_agg2)[idx] = o;   // self-loop seed
}

// ---- K_scatter2: 4 adjacent edges/thread, int4 index loads, fp16 red ------
__global__ void k_scatter2(const int* __restrict__ src,
                           const int* __restrict__ dst) {
    int t = blockIdx.x * blockDim.x + threadIdx.x;
    if (t >= EQ4) return;
    int4 s4 = __ldg(&((const int4*)src)[t]);   // edges 4t .. 4t+3
    int4 d4 = __ldg(&((const int4*)dst)[t]);
    const uint4* hs = (const uint4*)g_hs2;
    uint4 a0 = __ldg(&hs[s4.x * 2]), a1 = __ldg(&hs[s4.x * 2 + 1]);
    uint4 b0 = __ldg(&hs[s4.y * 2]), b1 = __ldg(&hs[s4.y * 2 + 1]);
    uint4 c0 = __ldg(&hs[s4.z * 2]), c1 = __ldg(&hs[s4.z * 2 + 1]);
    uint4 e0 = __ldg(&hs[s4.w * 2]), e1 = __ldg(&hs[s4.w * 2 + 1]);
    __half* p0 = g_agg2 + d4.x * HIDDEN;
    __half* p1 = g_agg2 + d4.y * HIDDEN;
    __half* p2 = g_agg2 + d4.z * HIDDEN;
    __half* p3 = g_agg2 + d4.w * HIDDEN;
    red16(p0, a0); red16(p0 + 8, a1);
    red16(p1, b0); red16(p1 + 8, b1);
    red16(p2, c0); red16(p2 + 8, c1);
    red16(p3, e0); red16(p3 + 8, e1);
}

// ---- K_pool: pool += dinv[n]*agg2[n]  (batch sorted, run-length) ----------
#define POOL_CHUNK 32
__global__ void k_pool(const int* __restrict__ batch) {
    int t = blockIdx.x * blockDim.x + threadIdx.x;
    const int n_chunks = N_NODES / POOL_CHUNK;
    if (t >= n_chunks * HIDDEN) return;
    int c = t >> 4;
    int j = t & 15;
    int n0 = c * POOL_CHUNK;

    int   curg = __ldg(&batch[n0]);
    float acc  = 0.0f;
    float accc = 0.0f;
    for (int n = n0; n < n0 + POOL_CHUNK; n++) {
        int g = __ldg(&batch[n]);
        if (g != curg) {
            atomicAdd(&g_pool[curg * HIDDEN + j], acc);
            if (j == 0) atomicAdd(&g_cnt[curg], accc);
            acc = 0.0f; accc = 0.0f; curg = g;
        }
        float v = __half2float(g_agg2[n * HIDDEN + j]);
        acc  = fmaf(g_dinv[n], v, acc);
        accc += 1.0f;
    }
    atomicAdd(&g_pool[curg * HIDDEN + j], acc);
    if (j == 0) atomicAdd(&g_cnt[curg], accc);
}

// ---- K_final: out = (pool/cnt) @ W2 + b2 -----------------------------------
__global__ void k_final(const float* __restrict__ W2,
                        const float* __restrict__ b2,
                        float* __restrict__ out) {
    int t = blockIdx.x * blockDim.x + threadIdx.x;
    if (t >= N_GRAPHS * EMBED) return;
    int g = t >> 7;
    int e = t & 127;
    float inv = 1.0f / fmaxf(g_cnt[g], 1.0f);
    float sum = 0.0f;
#pragma unroll
    for (int k = 0; k < HIDDEN; k++)
        sum += g_pool[g * HIDDEN + k] * W2[k * EMBED + e];
    out[t] = b2[e] + inv * sum;
}

// ---------------- launch ----------------------------------------------------
extern "C" void kernel_launch(void* const* d_in, const int* in_sizes, int n_in,
                              void* d_out, int out_size) {
    const float* x     = (const float*)d_in[0];
    const int*   ei    = (const int*)  d_in[1];
    const int*   batch = (const int*)  d_in[2];
    const float* W1    = (const float*)d_in[3];
    const float* b1    = (const float*)d_in[4];
    const float* W2    = (const float*)d_in[5];
    const float* b2    = (const float*)d_in[6];
    float* out = (float*)d_out;

    const int* src = ei;
    const int* dst = ei + N_EDGES;

    k_main<<<GEMM_BLOCKS + DEG_BLOCKS, 256>>>((const float4*)x, W1, dst);
    k_self<<<(N_NODES * 2 + 255) / 256, 256>>>();
    k_scatter1<<<(EQ4 + 255) / 256, 256>>>(src, dst);
    k_relu<<<(N_NODES * 2 + 255) / 256, 256>>>(b1);
    k_scatter2<<<(EQ4 + 255) / 256, 256>>>(src, dst);
    k_pool<<<((N_NODES / POOL_CHUNK) * HIDDEN + 255) / 256, 256>>>(batch);
    k_final<<<(N_GRAPHS * EMBED + 255) / 256, 256>>>(W2, b2, out);
}

// round 17
// speedup vs baseline: 1.0480x; 1.0226x over previous
#include <cuda_runtime.h>
#include <cuda_fp16.h>
#include <math.h>

#define N_NODES   100000
#define N_EDGES   1600000
#define N_FEAT    128
#define HIDDEN    16
#define EMBED     128
#define N_GRAPHS  64

// ---------------- scratch (device globals; no allocation allowed) ----------
// Zero-initialized at load; cross-call resets of g_degi/g_pool/g_cnt are
// folded into k_relu (after last reader, before next user).
__device__ __align__(16) int    g_degi[N_NODES];
__device__ __align__(16) float  g_dinv[N_NODES];
__device__ __align__(16) __half g_h1  [N_NODES * HIDDEN];   // x@W1, fp16
__device__ __align__(16) __half g_hs1 [N_NODES * HIDDEN];   // dinv*h1, fp16
__device__ __align__(16) __half g_agg1[N_NODES * HIDDEN];   // fp16 accumulator
__device__ __align__(16) __half g_hs2 [N_NODES * HIDDEN];   // dinv*hrelu, fp16
__device__ __align__(16) __half g_agg2[N_NODES * HIDDEN];   // fp16 accumulator
__device__ __align__(16) float  g_pool[N_GRAPHS * HIDDEN];
__device__ __align__(16) float  g_cnt [N_GRAPHS];

// ---------------- packed-math helpers ---------------------------------------
__device__ __forceinline__ unsigned long long pack2(float a, float b) {
    unsigned long long r;
    asm("mov.b64 %0, {%1, %2};" : "=l"(r) : "f"(a), "f"(b));
    return r;
}
__device__ __forceinline__ unsigned long long fma2(unsigned long long a,
                                                   unsigned long long b,
                                                   unsigned long long c) {
    unsigned long long d;
    asm("fma.rn.f32x2 %0, %1, %2, %3;" : "=l"(d) : "l"(a), "l"(b), "l"(c));
    return d;
}
// f32x2 (packed in u64) -> half2 (packed in u32)
__device__ __forceinline__ unsigned ull2h2(unsigned long long v) {
    float lo, hi;
    asm("mov.b64 {%0, %1}, %2;" : "=f"(lo), "=f"(hi) : "l"(v));
    __half2 h = __floats2half2_rn(lo, hi);
    return *(unsigned*)&h;
}
__device__ __forceinline__ void red16(__half* p, uint4 u) {
    asm volatile("red.global.add.noftz.v4.f16x2 [%0], {%1,%2,%3,%4};"
                 :: "l"(p), "r"(u.x), "r"(u.y), "r"(u.z), "r"(u.w) : "memory");
}

// ---------------- K_main: fused [GEMM1 h1 = x@W1 (fp16 out)] + [degree] ----
#define NPB   512
#define KC    16
#define PITCH 513
#define GEMM_BLOCKS ((N_NODES + NPB - 1) / NPB)   // 196
#define DEG_BLOCKS  (N_EDGES / 256)               // 6250 (divides exactly)
__global__ __launch_bounds__(256) void k_main(const float4* __restrict__ x4,
                                              const float*  __restrict__ W1,
                                              const int*    __restrict__ dst) {
    if (blockIdx.x >= GEMM_BLOCKS) {
        int e = (blockIdx.x - GEMM_BLOCKS) * 256 + threadIdx.x;
        if (e < N_EDGES) atomicAdd(&g_degi[dst[e]], 1);
        return;
    }

    __shared__ float xs[KC * PITCH];                     // k-major x tile
    __shared__ unsigned long long Wp[N_FEAT * HIDDEN/2]; // packed W pairs

    int tid = threadIdx.x;
    for (int i = tid; i < N_FEAT * HIDDEN / 2; i += 256) {
        float2 w = ((const float2*)W1)[i];
        Wp[i] = pack2(w.x, w.y);
    }

    int base = blockIdx.x * NPB;
    int na = base + tid;
    int nb = na + 256;

    unsigned long long accA[8], accB[8];
    unsigned long long z = pack2(0.0f, 0.0f);
#pragma unroll
    for (int p = 0; p < 8; p++) { accA[p] = z; accB[p] = z; }

    for (int c = 0; c < N_FEAT / KC; c++) {
        __syncthreads();
#pragma unroll
        for (int i = 0; i < 8; i++) {
            int idx = i * 256 + tid;
            int q = idx & 3;
            int n = idx >> 2;
            int gn = base + n;
            if (gn >= N_NODES) gn = 0;
            float4 v = x4[gn * (N_FEAT/4) + c * (KC/4) + q];
            int kb = 4 * q;
            xs[(kb + 0) * PITCH + n] = v.x;
            xs[(kb + 1) * PITCH + n] = v.y;
            xs[(kb + 2) * PITCH + n] = v.z;
            xs[(kb + 3) * PITCH + n] = v.w;
        }
        __syncthreads();

#pragma unroll
        for (int k = 0; k < KC; k++) {
            float xa = xs[k * PITCH + tid];
            float xb = xs[k * PITCH + tid + 256];
            unsigned long long xa2 = pack2(xa, xa);
            unsigned long long xb2 = pack2(xb, xb);
            int kg = c * KC + k;
#pragma unroll
            for (int p2 = 0; p2 < 4; p2++) {
                ulonglong2 w = *((const ulonglong2*)&Wp[kg * 8 + 2 * p2]);
                accA[2*p2]   = fma2(xa2, w.x, accA[2*p2]);
                accA[2*p2+1] = fma2(xa2, w.y, accA[2*p2+1]);
                accB[2*p2]   = fma2(xb2, w.x, accB[2*p2]);
                accB[2*p2+1] = fma2(xb2, w.y, accB[2*p2+1]);
            }
        }
    }

    if (na < N_NODES) {
        uint4 o0, o1;
        o0.x = ull2h2(accA[0]); o0.y = ull2h2(accA[1]);
        o0.z = ull2h2(accA[2]); o0.w = ull2h2(accA[3]);
        o1.x = ull2h2(accA[4]); o1.y = ull2h2(accA[5]);
        o1.z = ull2h2(accA[6]); o1.w = ull2h2(accA[7]);
        ((uint4*)g_h1)[na * 2]     = o0;
        ((uint4*)g_h1)[na * 2 + 1] = o1;
    }
    if (nb < N_NODES) {
        uint4 o0, o1;
        o0.x = ull2h2(accB[0]); o0.y = ull2h2(accB[1]);
        o0.z = ull2h2(accB[2]); o0.w = ull2h2(accB[3]);
        o1.x = ull2h2(accB[4]); o1.y = ull2h2(accB[5]);
        o1.z = ull2h2(accB[6]); o1.w = ull2h2(accB[7]);
        ((uint4*)g_h1)[nb * 2]     = o0;
        ((uint4*)g_h1)[nb * 2 + 1] = o1;
    }
}

// ---- K_self: dinv = rsqrt(1+deg); hs1 = agg1 seed = dinv*h1 (fp16 in/out) -
__global__ void k_self() {
    int idx = blockIdx.x * blockDim.x + threadIdx.x;   // over uint4 (8 halves)
    if (idx >= N_NODES * 2) return;
    int node = idx >> 1;
    float di = rsqrtf(1.0f + (float)g_degi[node]);
    if ((idx & 1) == 0) g_dinv[node] = di;
    uint4 u = ((const uint4*)g_h1)[idx];
    float2 f0 = __half22float2(*(__half2*)&u.x);
    float2 f1 = __half22float2(*(__half2*)&u.y);
    float2 f2 = __half22float2(*(__half2*)&u.z);
    float2 f3 = __half22float2(*(__half2*)&u.w);
    __half2 h0 = __floats2half2_rn(f0.x * di, f0.y * di);
    __half2 h1 = __floats2half2_rn(f1.x * di, f1.y * di);
    __half2 h2 = __floats2half2_rn(f2.x * di, f2.y * di);
    __half2 h3 = __floats2half2_rn(f3.x * di, f3.y * di);
    uint4 o;
    o.x = *(unsigned*)&h0; o.y = *(unsigned*)&h1;
    o.z = *(unsigned*)&h2; o.w = *(unsigned*)&h3;
    ((uint4*)g_hs1)[idx]  = o;
    ((uint4*)g_agg1)[idx] = o;   // self-loop seed
}

// ---- K_scatter1: 2 adjacent edges/thread, int2 index loads, fp16 red ------
#define EHALF (N_EDGES / 2)
__global__ void k_scatter1(const int* __restrict__ src,
                           const int* __restrict__ dst) {
    int t = blockIdx.x * blockDim.x + threadIdx.x;
    if (t >= EHALF) return;
    int2 s2 = __ldg(&((const int2*)src)[t]);   // edges 2t, 2t+1
    int2 d2 = __ldg(&((const int2*)dst)[t]);
    const uint4* hs = (const uint4*)g_hs1;
    uint4 a0 = __ldg(&hs[s2.x * 2]);
    uint4 a1 = __ldg(&hs[s2.x * 2 + 1]);
    uint4 b0 = __ldg(&hs[s2.y * 2]);
    uint4 b1 = __ldg(&hs[s2.y * 2 + 1]);
    __half* pa = g_agg1 + d2.x * HIDDEN;
    __half* pb = g_agg1 + d2.y * HIDDEN;
    red16(pa,     a0);
    red16(pa + 8, a1);
    red16(pb,     b0);
    red16(pb + 8, b1);
}

// ---- K_relu: relu layer + fold-in resets of degi/pool/cnt for next call ---
__global__ void k_relu(const float* __restrict__ b1) {
    int idx = blockIdx.x * blockDim.x + threadIdx.x;    // over uint4 (8 halves)
    if (idx < N_NODES / 4) ((int4*)g_degi)[idx] = make_int4(0, 0, 0, 0);
    if (idx < N_GRAPHS * HIDDEN / 4)
        ((float4*)g_pool)[idx] = make_float4(0.f, 0.f, 0.f, 0.f);
    if (idx < N_GRAPHS / 4)
        ((float4*)g_cnt)[idx] = make_float4(0.f, 0.f, 0.f, 0.f);

    if (idx >= N_NODES * 2) return;
    int node  = idx >> 1;
    int half8 = idx & 1;
    float di = g_dinv[node];
    uint4 u = ((const uint4*)g_agg1)[idx];
    float4 blo = ((const float4*)b1)[half8 * 2];
    float4 bhi = ((const float4*)b1)[half8 * 2 + 1];
    float2 f0 = __half22float2(*(__half2*)&u.x);
    float2 f1 = __half22float2(*(__half2*)&u.y);
    float2 f2 = __half22float2(*(__half2*)&u.z);
    float2 f3 = __half22float2(*(__half2*)&u.w);
    f0.x = fmaxf(fmaf(di, f0.x, blo.x), 0.0f) * di;
    f0.y = fmaxf(fmaf(di, f0.y, blo.y), 0.0f) * di;
    f1.x = fmaxf(fmaf(di, f1.x, blo.z), 0.0f) * di;
    f1.y = fmaxf(fmaf(di, f1.y, blo.w), 0.0f) * di;
    f2.x = fmaxf(fmaf(di, f2.x, bhi.x), 0.0f) * di;
    f2.y = fmaxf(fmaf(di, f2.y, bhi.y), 0.0f) * di;
    f3.x = fmaxf(fmaf(di, f3.x, bhi.z), 0.0f) * di;
    f3.y = fmaxf(fmaf(di, f3.y, bhi.w), 0.0f) * di;
    __half2 h0 = __floats2half2_rn(f0.x, f0.y);
    __half2 h1 = __floats2half2_rn(f1.x, f1.y);
    __half2 h2 = __floats2half2_rn(f2.x, f2.y);
    __half2 h3 = __floats2half2_rn(f3.x, f3.y);
    uint4 o;
    o.x = *(unsigned*)&h0; o.y = *(unsigned*)&h1;
    o.z = *(unsigned*)&h2; o.w = *(unsigned*)&h3;
    ((uint4*)g_hs2)[idx]  = o;
    ((uint4*)g_agg2)[idx] = o;   // self-loop seed
}

// ---- K_scatter2: 2 adjacent edges/thread, int2 index loads, fp16 red ------
__global__ void k_scatter2(const int* __restrict__ src,
                           const int* __restrict__ dst) {
    int t = blockIdx.x * blockDim.x + threadIdx.x;
    if (t >= EHALF) return;
    int2 s2 = __ldg(&((const int2*)src)[t]);   // edges 2t, 2t+1
    int2 d2 = __ldg(&((const int2*)dst)[t]);
    const uint4* hs = (const uint4*)g_hs2;
    uint4 a0 = __ldg(&hs[s2.x * 2]);
    uint4 a1 = __ldg(&hs[s2.x * 2 + 1]);
    uint4 b0 = __ldg(&hs[s2.y * 2]);
    uint4 b1 = __ldg(&hs[s2.y * 2 + 1]);
    __half* pa = g_agg2 + d2.x * HIDDEN;
    __half* pb = g_agg2 + d2.y * HIDDEN;
    red16(pa,     a0);
    red16(pa + 8, a1);
    red16(pb,     b0);
    red16(pb + 8, b1);
}

// ---- K_pool: pool += dinv[n]*agg2[n]  (batch sorted, run-length) ----------
#define POOL_CHUNK 32
__global__ void k_pool(const int* __restrict__ batch) {
    int t = blockIdx.x * blockDim.x + threadIdx.x;
    const int n_chunks = N_NODES / POOL_CHUNK;
    if (t >= n_chunks * HIDDEN) return;
    int c = t >> 4;
    int j = t & 15;
    int n0 = c * POOL_CHUNK;

    int   curg = __ldg(&batch[n0]);
    float acc  = 0.0f;
    float accc = 0.0f;
    for (int n = n0; n < n0 + POOL_CHUNK; n++) {
        int g = __ldg(&batch[n]);
        if (g != curg) {
            atomicAdd(&g_pool[curg * HIDDEN + j], acc);
            if (j == 0) atomicAdd(&g_cnt[curg], accc);
            acc = 0.0f; accc = 0.0f; curg = g;
        }
        float v = __half2float(g_agg2[n * HIDDEN + j]);
        acc  = fmaf(g_dinv[n], v, acc);
        accc += 1.0f;
    }
    atomicAdd(&g_pool[curg * HIDDEN + j], acc);
    if (j == 0) atomicAdd(&g_cnt[curg], accc);
}

// ---- K_final: out = (pool/cnt) @ W2 + b2 -----------------------------------
__global__ void k_final(const float* __restrict__ W2,
                        const float* __restrict__ b2,
                        float* __restrict__ out) {
    int t = blockIdx.x * blockDim.x + threadIdx.x;
    if (t >= N_GRAPHS * EMBED) return;
    int g = t >> 7;
    int e = t & 127;
    float inv = 1.0f / fmaxf(g_cnt[g], 1.0f);
    float sum = 0.0f;
#pragma unroll
    for (int k = 0; k < HIDDEN; k++)
        sum += g_pool[g * HIDDEN + k] * W2[k * EMBED + e];
    out[t] = b2[e] + inv * sum;
}

// ---------------- launch ----------------------------------------------------
extern "C" void kernel_launch(void* const* d_in, const int* in_sizes, int n_in,
                              void* d_out, int out_size) {
    const float* x     = (const float*)d_in[0];
    const int*   ei    = (const int*)  d_in[1];
    const int*   batch = (const int*)  d_in[2];
    const float* W1    = (const float*)d_in[3];
    const float* b1    = (const float*)d_in[4];
    const float* W2    = (const float*)d_in[5];
    const float* b2    = (const float*)d_in[6];
    float* out = (float*)d_out;

    const int* src = ei;
    const int* dst = ei + N_EDGES;

    k_main<<<GEMM_BLOCKS + DEG_BLOCKS, 256>>>((const float4*)x, W1, dst);
    k_self<<<(N_NODES * 2 + 255) / 256, 256>>>();
    k_scatter1<<<(EHALF + 255) / 256, 256>>>(src, dst);
    k_relu<<<(N_NODES * 2 + 255) / 256, 256>>>(b1);
    k_scatter2<<<(EHALF + 255) / 256, 256>>>(src, dst);
    k_pool<<<((N_NODES / POOL_CHUNK) * HIDDEN + 255) / 256, 256>>>(batch);
    k_final<<<(N_GRAPHS * EMBED + 255) / 256, 256>>>(W2, b2, out);
}